// round 11
// baseline (speedup 1.0000x reference)
#include <cuda_runtime.h>

typedef unsigned long long u64;

__device__ __forceinline__ void fma2(u64& d, u64 a, u64 b) {
    asm("fma.rn.f32x2 %0, %1, %2, %0;" : "+l"(d) : "l"(a), "l"(b));
}

// ---------------------------------------------------------------------------
// Single fused kernel. 296 persistent blocks x 256 threads (2 blocks/SM).
//
// Startup (in-kernel weight fold, replaces the former prep kernel+launch):
//   Warp wid owns ci-pair wid. In 2 rounds (warps 0-3, then 4-7), each warp
//   copies its raw weight slice w[2*wid..2*wid+1][32co][27] (1728 contiguous
//   floats) coalesced into smem scratch, then lane co computes the 27 folded
//   tap-sums for both ci of the pair, scaled by gamma/sqrt(var+eps)/64, and
//   packs them into 27 register-pinned f32x2 values.
//   Tap sets per residue r (z = 2i-1+k, z-offset in [0,3]):
//     T(0)={1,2}, T(1)={0,1,2}, T(2)={0}
//
// Steady state (identical to R10): block processes tiles bid, bid+296, ...
//   x tile staged ci-pair-interleaved into double-buffered smem; next tile's
//   LDG.128s issue before current compute; streamed f32x2 FMA over 11 ow
//   accumulators; cross-warp reduce via smem; store with fused BN constant.
// ---------------------------------------------------------------------------
__global__ __launch_bounds__(256, 2)
void conv_fused_kernel(const float* __restrict__ x,
                       const float* __restrict__ wsrc,
                       const float* __restrict__ bias,
                       const float* __restrict__ gamma,
                       const float* __restrict__ beta,
                       const float* __restrict__ mean,
                       const float* __restrict__ var,
                       float* __restrict__ out) {
    __shared__ __align__(16) u64 xs2[2][8 * 9 * 24];   // 27648 B (also fold scratch)
    __shared__ float red[8][352];                      // 11264 B

    const int tid  = threadIdx.x;
    const int lane = tid & 31;   // co
    const int wid  = tid >> 5;   // ci pair

    // ================= in-kernel weight fold =================
    const float scale = __ldg(&gamma[lane]) * rsqrtf(__ldg(&var[lane]) + 1e-5f);
    const float cb = __ldg(&bias[lane]) * scale + __ldg(&beta[lane])
                   - __ldg(&mean[lane]) * scale;

    u64 wr[27];
    {
        float* scr = reinterpret_cast<float*>(xs2) + (wid & 3) * 1728;
        const int st[3] = {1, 0, 0};
        const int en[3] = {3, 3, 1};
#pragma unroll 1
        for (int round = 0; round < 2; ++round) {
            if ((wid >> 2) == round) {
                // coalesced copy of this pair's raw slice (1728 floats)
                const float4* src = reinterpret_cast<const float4*>(
                    wsrc + (size_t)wid * 1728);
                float4* dst = reinterpret_cast<float4*>(scr);
#pragma unroll 1
                for (int i = lane; i < 432; i += 32) dst[i] = __ldg(src + i);
                __syncwarp();

                // fold: lane co, both ci of the pair
                const float* s0p = scr + lane * 27;          // ci = 2*wid
                const float* s1p = scr + (32 + lane) * 27;    // ci = 2*wid+1
#pragma unroll 1
                for (int r3 = 0; r3 < 27; ++r3) {
                    int rd = r3 / 9, rh = (r3 / 3) % 3, rw = r3 % 3;
                    float a0 = 0.f, a1 = 0.f;
                    for (int kd = st[rd]; kd < en[rd]; ++kd)
                        for (int kh = st[rh]; kh < en[rh]; ++kh)
                            for (int kw = st[rw]; kw < en[rw]; ++kw) {
                                int k = kd * 9 + kh * 3 + kw;
                                a0 += s0p[k];
                                a1 += s1p[k];
                            }
                    float v0 = a0 * scale * (1.f / 64.f);
                    float v1 = a1 * scale * (1.f / 64.f);
                    asm("mov.b64 %0, {%1, %2};" : "=l"(wr[r3]) : "f"(v0), "f"(v1));
                }
            }
            __syncthreads();   // round scratch handoff / fold complete
        }
    }

    // ================= staging task decode (hoisted) =================
    const int p0  = tid / 54, u0 = tid - p0 * 54;
    const int rr0 = u0 / 6,  q0 = u0 - rr0 * 6;
    const int so0 = 2 * p0 * 13824 + (rr0 / 3) * 576 + (rr0 % 3) * 24 + 4 * q0;
    const int df0 = (p0 * 9 + rr0) * 12 + 2 * q0;      // float4 index in xs2

    const bool h1 = (tid < 176);
    const int t1  = tid + 256;
    const int p1  = t1 / 54, u1 = t1 - p1 * 54;
    const int rr1 = u1 / 6,  q1 = u1 - rr1 * 6;
    const int so1 = 2 * p1 * 13824 + (rr1 / 3) * 576 + (rr1 % 3) * 24 + 4 * q1;
    const int df1 = (p1 * 9 + rr1) * 12 + 2 * q1;

    const int nt = (blockIdx.x < 80) ? 4 : 3;   // 80*4 + 216*3 = 968 tiles

    // ================= prologue: stage tile 0 =================
    {
        int gw = blockIdx.x;
        int b = gw / 121, rem = gw - b * 121, od = rem / 11, oh = rem - od * 11;
        const float* xb = x + (size_t)b * 221184 + (2 * od) * 576 + (2 * oh) * 24;
        float4 A0 = __ldg(reinterpret_cast<const float4*>(xb + so0));
        float4 B0 = __ldg(reinterpret_cast<const float4*>(xb + so0 + 13824));
        float4* d = reinterpret_cast<float4*>(xs2[0]);
        d[df0]     = make_float4(A0.x, B0.x, A0.y, B0.y);
        d[df0 + 1] = make_float4(A0.z, B0.z, A0.w, B0.w);
        if (h1) {
            float4 A1 = __ldg(reinterpret_cast<const float4*>(xb + so1));
            float4 B1 = __ldg(reinterpret_cast<const float4*>(xb + so1 + 13824));
            d[df1]     = make_float4(A1.x, B1.x, A1.y, B1.y);
            d[df1 + 1] = make_float4(A1.z, B1.z, A1.w, B1.w);
        }
    }
    __syncthreads();

    // ================= main loop =================
#pragma unroll 1
    for (int it = 0; it < nt; ++it) {
        const int gw = blockIdx.x + it * 296;
        const int b = gw / 121, rem = gw - b * 121;
        const int od = rem / 11, oh = rem - od * 11;

        // issue next tile's loads early (latency hides under compute)
        const bool more = (it + 1) < nt;
        float4 A0, B0, A1, B1;
        if (more) {
            int gn = gw + 296;
            int bn = gn / 121, rn = gn - bn * 121, odn = rn / 11, ohn = rn - odn * 11;
            const float* xb = x + (size_t)bn * 221184 + (2 * odn) * 576 + (2 * ohn) * 24;
            A0 = __ldg(reinterpret_cast<const float4*>(xb + so0));
            B0 = __ldg(reinterpret_cast<const float4*>(xb + so0 + 13824));
            if (h1) {
                A1 = __ldg(reinterpret_cast<const float4*>(xb + so1));
                B1 = __ldg(reinterpret_cast<const float4*>(xb + so1 + 13824));
            }
        }

        // compute: streamed x, weights in regs
        const u64* xw = xs2[it & 1] + wid * 216;
        u64 acc[11];
#pragma unroll
        for (int i = 0; i < 11; ++i) acc[i] = 0ull;

#pragma unroll
        for (int rr = 0; rr < 9; ++rr) {
            const ulonglong2* rp = reinterpret_cast<const ulonglong2*>(xw + rr * 24);
            ulonglong2 tt = rp[0];
            u64 x0 = tt.x, x1 = tt.y;
#pragma unroll
            for (int ow = 0; ow < 11; ++ow) {
                ulonglong2 tn = rp[ow + 1];
                fma2(acc[ow], wr[rr * 3 + 0], x0);
                fma2(acc[ow], wr[rr * 3 + 1], x1);
                fma2(acc[ow], wr[rr * 3 + 2], tn.x);
                x0 = tn.x;
                x1 = tn.y;
            }
        }

#pragma unroll
        for (int ow = 0; ow < 11; ++ow) {
            float lo, hi;
            asm("mov.b64 {%0, %1}, %2;" : "=f"(lo), "=f"(hi) : "l"(acc[ow]));
            red[wid][ow * 32 + lane] = lo + hi;
        }
        __syncthreads();   // red ready; all reads of xs2[(it+1)&1] long done

        // stage next tile
        if (more) {
            float4* d = reinterpret_cast<float4*>(xs2[(it + 1) & 1]);
            d[df0]     = make_float4(A0.x, B0.x, A0.y, B0.y);
            d[df0 + 1] = make_float4(A0.z, B0.z, A0.w, B0.w);
            if (h1) {
                d[df1]     = make_float4(A1.x, B1.x, A1.y, B1.y);
                d[df1 + 1] = make_float4(A1.z, B1.z, A1.w, B1.w);
            }
        }

        // store current tile (co = lane since 256 % 32 == 0)
        {
            float s0 = cb;
#pragma unroll
            for (int w = 0; w < 8; ++w) s0 += red[w][tid >= 352 ? 0 : tid];
            if (tid < 352)
                out[((size_t)(b * 32 + lane)) * 1331 + od * 121 + oh * 11 + (tid >> 5)] = s0;
            if (tid < 96) {
                int j = tid + 256;
                float s1 = cb;
#pragma unroll
                for (int w = 0; w < 8; ++w) s1 += red[w][j];
                out[((size_t)(b * 32 + lane)) * 1331 + od * 121 + oh * 11 + (j >> 5)] = s1;
            }
        }
        __syncthreads();   // red consumed + next x buffer visible
    }
}

extern "C" void kernel_launch(void* const* d_in, const int* in_sizes, int n_in,
                              void* d_out, int out_size) {
    const float* x     = (const float*)d_in[0];
    const float* w     = (const float*)d_in[1];
    const float* bias  = (const float*)d_in[2];
    const float* gamma = (const float*)d_in[3];
    const float* beta  = (const float*)d_in[4];
    const float* mean  = (const float*)d_in[5];
    const float* var   = (const float*)d_in[6];
    float* out = (float*)d_out;

    conv_fused_kernel<<<296, 256>>>(x, w, bias, gamma, beta, mean, var, out);
}

// round 12
// speedup vs baseline: 3.4907x; 3.4907x over previous
#include <cuda_runtime.h>

typedef unsigned long long u64;

__device__ __forceinline__ void fma2(u64& d, u64 a, u64 b) {
    asm("fma.rn.f32x2 %0, %1, %2, %0;" : "+l"(d) : "l"(a), "l"(b));
}

// Separable tap-set fold, fully unrolled, compile-time indices only.
// o[rd*9+rh*3+rw] = sc * sum_{kd in T(rd), kh in T(rh), kw in T(rw)} a[kd*9+kh*3+kw]
// with T(0)={1,2}, T(1)={0,1,2}, T(2)={0}.
__device__ __forceinline__ void fold27(const float* __restrict__ a, float sc,
                                       float* __restrict__ o) {
    float c[27];
#pragma unroll
    for (int j = 0; j < 9; ++j) {            // fold w axis
        float i0 = a[3 * j], i1 = a[3 * j + 1], i2 = a[3 * j + 2];
        float t = i1 + i2;
        c[3 * j + 0] = t; c[3 * j + 1] = t + i0; c[3 * j + 2] = i0;
    }
    float d[27];
#pragma unroll
    for (int kd = 0; kd < 3; ++kd)           // fold h axis
#pragma unroll
        for (int rw = 0; rw < 3; ++rw) {
            float r0 = c[(3 * kd + 0) * 3 + rw];
            float r1 = c[(3 * kd + 1) * 3 + rw];
            float r2 = c[(3 * kd + 2) * 3 + rw];
            float t = r1 + r2;
            d[(kd * 3 + 0) * 3 + rw] = t;
            d[(kd * 3 + 1) * 3 + rw] = t + r0;
            d[(kd * 3 + 2) * 3 + rw] = r0;
        }
#pragma unroll
    for (int rh = 0; rh < 3; ++rh)           // fold d axis + scale
#pragma unroll
        for (int rw = 0; rw < 3; ++rw) {
            float r0 = d[(0 * 3 + rh) * 3 + rw];
            float r1 = d[(1 * 3 + rh) * 3 + rw];
            float r2 = d[(2 * 3 + rh) * 3 + rw];
            float t = r1 + r2;
            o[(0 * 3 + rh) * 3 + rw] = t * sc;
            o[(1 * 3 + rh) * 3 + rw] = (t + r0) * sc;
            o[(2 * 3 + rh) * 3 + rw] = r0 * sc;
        }
}

// ---------------------------------------------------------------------------
// Single fused kernel. 296 persistent blocks x 256 threads (2 blocks/SM).
//
// Startup: warp wid folds its ci-pair's weights into 27 register-pinned f32x2.
//   Per ci phase: 864 contiguous floats (w[ci][co][k], torch layout
//   (Cin,Cout,3,3,3)) copied coalesced into this warp's 3456B smem slice,
//   then lane co reads its 27 raw taps (stride-27 LDS: gcd(27,32)=1 ->
//   conflict-free) and runs the straight-line fold above. Only __syncwarp
//   inside; one __syncthreads before the scratch is reused for x staging.
//
// Steady state (R10, best measured): block processes tiles bid, bid+296, ...
//   (tile = (b,od,oh)); x staged ci-pair-interleaved into double-buffered
//   smem; next tile's LDG.128s issue before current compute; streamed
//   fma.rn.f32x2 over 11 ow accumulators; cross-warp reduce via smem;
//   store with fused BN constant.
// ---------------------------------------------------------------------------
__global__ __launch_bounds__(256, 2)
void conv_fused_kernel(const float* __restrict__ x,
                       const float* __restrict__ wsrc,
                       const float* __restrict__ bias,
                       const float* __restrict__ gamma,
                       const float* __restrict__ beta,
                       const float* __restrict__ mean,
                       const float* __restrict__ var,
                       float* __restrict__ out) {
    __shared__ __align__(16) u64 xs2[2][8 * 9 * 24];   // 27648 B (fold scratch too)
    __shared__ float red[8][352];                      // 11264 B

    const int tid  = threadIdx.x;
    const int lane = tid & 31;   // co
    const int wid  = tid >> 5;   // ci pair

    // ================= in-kernel weight fold =================
    const float scale = __ldg(&gamma[lane]) * rsqrtf(__ldg(&var[lane]) + 1e-5f);
    const float cb = __ldg(&bias[lane]) * scale + __ldg(&beta[lane])
                   - __ldg(&mean[lane]) * scale;
    const float sc64 = scale * (1.f / 64.f);

    u64 wr[27];
    {
        float* scr = reinterpret_cast<float*>(xs2) + wid * 864;   // 3456 B/warp
        float o0[27], o1[27];
#pragma unroll 1
        for (int ph = 0; ph < 2; ++ph) {   // ci = 2*wid + ph
            const float4* src = reinterpret_cast<const float4*>(
                wsrc + (size_t)(2 * wid + ph) * 864);
            float4* dst = reinterpret_cast<float4*>(scr);
#pragma unroll
            for (int k = 0; k < 7; ++k) {                 // 216 float4, coalesced
                int i = lane + k * 32;
                if (i < 216) dst[i] = __ldg(src + i);
            }
            __syncwarp();
            float a[27];
            const float* ap = scr + lane * 27;            // conflict-free LDS
#pragma unroll
            for (int k = 0; k < 27; ++k) a[k] = ap[k];
            fold27(a, sc64, ph ? o1 : o0);
            __syncwarp();                                  // before overwrite
        }
#pragma unroll
        for (int r = 0; r < 27; ++r)
            asm("mov.b64 %0, {%1, %2};" : "=l"(wr[r]) : "f"(o0[r]), "f"(o1[r]));
    }
    __syncthreads();   // scratch free; fold complete everywhere

    // ================= staging task decode (hoisted) =================
    const int p0  = tid / 54, u0 = tid - p0 * 54;
    const int rr0 = u0 / 6,  q0 = u0 - rr0 * 6;
    const int so0 = 2 * p0 * 13824 + (rr0 / 3) * 576 + (rr0 % 3) * 24 + 4 * q0;
    const int df0 = (p0 * 9 + rr0) * 12 + 2 * q0;      // float4 index in xs2

    const bool h1 = (tid < 176);
    const int t1  = tid + 256;
    const int p1  = t1 / 54, u1 = t1 - p1 * 54;
    const int rr1 = u1 / 6,  q1 = u1 - rr1 * 6;
    const int so1 = 2 * p1 * 13824 + (rr1 / 3) * 576 + (rr1 % 3) * 24 + 4 * q1;
    const int df1 = (p1 * 9 + rr1) * 12 + 2 * q1;

    const int nt = (blockIdx.x < 80) ? 4 : 3;   // 80*4 + 216*3 = 968 tiles

    // ================= prologue: stage tile 0 =================
    {
        int gw = blockIdx.x;
        int b = gw / 121, rem = gw - b * 121, od = rem / 11, oh = rem - od * 11;
        const float* xb = x + (size_t)b * 221184 + (2 * od) * 576 + (2 * oh) * 24;
        float4 A0 = __ldg(reinterpret_cast<const float4*>(xb + so0));
        float4 B0 = __ldg(reinterpret_cast<const float4*>(xb + so0 + 13824));
        float4* d = reinterpret_cast<float4*>(xs2[0]);
        d[df0]     = make_float4(A0.x, B0.x, A0.y, B0.y);
        d[df0 + 1] = make_float4(A0.z, B0.z, A0.w, B0.w);
        if (h1) {
            float4 A1 = __ldg(reinterpret_cast<const float4*>(xb + so1));
            float4 B1 = __ldg(reinterpret_cast<const float4*>(xb + so1 + 13824));
            d[df1]     = make_float4(A1.x, B1.x, A1.y, B1.y);
            d[df1 + 1] = make_float4(A1.z, B1.z, A1.w, B1.w);
        }
    }
    __syncthreads();

    // ================= main loop =================
#pragma unroll 1
    for (int it = 0; it < nt; ++it) {
        const int gw = blockIdx.x + it * 296;
        const int b = gw / 121, rem = gw - b * 121;
        const int od = rem / 11, oh = rem - od * 11;

        // issue next tile's loads early (latency hides under compute)
        const bool more = (it + 1) < nt;
        float4 A0, B0, A1, B1;
        if (more) {
            int gn = gw + 296;
            int bn = gn / 121, rn = gn - bn * 121, odn = rn / 11, ohn = rn - odn * 11;
            const float* xb = x + (size_t)bn * 221184 + (2 * odn) * 576 + (2 * ohn) * 24;
            A0 = __ldg(reinterpret_cast<const float4*>(xb + so0));
            B0 = __ldg(reinterpret_cast<const float4*>(xb + so0 + 13824));
            if (h1) {
                A1 = __ldg(reinterpret_cast<const float4*>(xb + so1));
                B1 = __ldg(reinterpret_cast<const float4*>(xb + so1 + 13824));
            }
        }

        // compute: streamed x, weights in regs
        const u64* xw = xs2[it & 1] + wid * 216;
        u64 acc[11];
#pragma unroll
        for (int i = 0; i < 11; ++i) acc[i] = 0ull;

#pragma unroll
        for (int rr = 0; rr < 9; ++rr) {
            const ulonglong2* rp = reinterpret_cast<const ulonglong2*>(xw + rr * 24);
            ulonglong2 tt = rp[0];
            u64 x0 = tt.x, x1 = tt.y;
#pragma unroll
            for (int ow = 0; ow < 11; ++ow) {
                ulonglong2 tn = rp[ow + 1];
                fma2(acc[ow], wr[rr * 3 + 0], x0);
                fma2(acc[ow], wr[rr * 3 + 1], x1);
                fma2(acc[ow], wr[rr * 3 + 2], tn.x);
                x0 = tn.x;
                x1 = tn.y;
            }
        }

#pragma unroll
        for (int ow = 0; ow < 11; ++ow) {
            float lo, hi;
            asm("mov.b64 {%0, %1}, %2;" : "=f"(lo), "=f"(hi) : "l"(acc[ow]));
            red[wid][ow * 32 + lane] = lo + hi;
        }
        __syncthreads();   // red ready; all reads of xs2[(it+1)&1] long done

        // stage next tile
        if (more) {
            float4* d = reinterpret_cast<float4*>(xs2[(it + 1) & 1]);
            d[df0]     = make_float4(A0.x, B0.x, A0.y, B0.y);
            d[df0 + 1] = make_float4(A0.z, B0.z, A0.w, B0.w);
            if (h1) {
                d[df1]     = make_float4(A1.x, B1.x, A1.y, B1.y);
                d[df1 + 1] = make_float4(A1.z, B1.z, A1.w, B1.w);
            }
        }

        // store current tile (co = lane since 256 % 32 == 0)
        {
            float s0 = cb;
#pragma unroll
            for (int w = 0; w < 8; ++w) s0 += red[w][tid >= 352 ? 0 : tid];
            if (tid < 352)
                out[((size_t)(b * 32 + lane)) * 1331 + od * 121 + oh * 11 + (tid >> 5)] = s0;
            if (tid < 96) {
                int j = tid + 256;
                float s1 = cb;
#pragma unroll
                for (int w = 0; w < 8; ++w) s1 += red[w][j];
                out[((size_t)(b * 32 + lane)) * 1331 + od * 121 + oh * 11 + (j >> 5)] = s1;
            }
        }
        __syncthreads();   // red consumed + next x buffer visible
    }
}

extern "C" void kernel_launch(void* const* d_in, const int* in_sizes, int n_in,
                              void* d_out, int out_size) {
    const float* x     = (const float*)d_in[0];
    const float* w     = (const float*)d_in[1];
    const float* bias  = (const float*)d_in[2];
    const float* gamma = (const float*)d_in[3];
    const float* beta  = (const float*)d_in[4];
    const float* mean  = (const float*)d_in[5];
    const float* var   = (const float*)d_in[6];
    float* out = (float*)d_out;

    conv_fused_kernel<<<296, 256>>>(x, w, bias, gamma, beta, mean, var, out);
}